// round 10
// baseline (speedup 1.0000x reference)
#include <cuda_runtime.h>
#include <cuda_bf16.h>
#include <cstdint>

// ---------------- problem constants ----------------
#define B_ROWS   65536
#define D_DIM    1024
#define E_N      10
#define U_N      10
#define NCOL     128          // padded N (120 used: 100 expert + 20 gate)
#define TILE_M   128
#define KC       64           // K elems per chunk (64 bf16 = 128B row)
#define NCHUNK   (D_DIM / KC) // 16
#define THREADS  512          // 16 warps: 4(M) x 4(N), warp tile 32x32

// smem: double-buffered A and B tiles (each 128 rows x 128B); epilogue D reuses
#define SMEM_TILE_B  (TILE_M * 128)     // 16KB
#define SMEM_A0   0
#define SMEM_A1   (SMEM_TILE_B)
#define SMEM_B0   (2 * SMEM_TILE_B)
#define SMEM_B1   (3 * SMEM_TILE_B)
#define D_STRIDE     129
#define SMEM_D_BYTES (TILE_M * D_STRIDE * 4)   // 66048 > 64KB of tiles
#define SMEM_DYN     (SMEM_D_BYTES + 1024)

// bf16 packed weights: Wb[n][k] (B^T, K-major). n<100: expert(u=n/10,e=n%10),
// n in [100,120): gate(t,e). Rest zero padding.
__device__ __nv_bfloat16 g_Wb[NCOL * D_DIM];

// ---------------- helpers ----------------
__device__ __forceinline__ uint32_t smem_u32(const void* p) {
    return (uint32_t)__cvta_generic_to_shared(p);
}
__device__ __forceinline__ uint32_t sw128(uint32_t off) {
    return off ^ ((off >> 3) & 0x70);
}
__device__ __forceinline__ void ldmat_x4(uint32_t& r0, uint32_t& r1,
                                         uint32_t& r2, uint32_t& r3,
                                         uint32_t addr) {
    asm volatile("ldmatrix.sync.aligned.m8n8.x4.shared.b16 {%0,%1,%2,%3}, [%4];"
                 : "=r"(r0), "=r"(r1), "=r"(r2), "=r"(r3) : "r"(addr));
}
__device__ __forceinline__ void mma_bf16(float* c, const uint32_t* a,
                                         uint32_t b0, uint32_t b1) {
    asm volatile(
        "mma.sync.aligned.m16n8k16.row.col.f32.bf16.bf16.f32 "
        "{%0,%1,%2,%3}, {%4,%5,%6,%7}, {%8,%9}, {%0,%1,%2,%3};"
        : "+f"(c[0]), "+f"(c[1]), "+f"(c[2]), "+f"(c[3])
        : "r"(a[0]), "r"(a[1]), "r"(a[2]), "r"(a[3]), "r"(b0), "r"(b1));
}
__device__ __forceinline__ void cp_async16(uint32_t dst, const void* src) {
    asm volatile("cp.async.ca.shared.global [%0], [%1], 16;"
                 :: "r"(dst), "l"(src));
}
__device__ __forceinline__ void cp_commit() {
    asm volatile("cp.async.commit_group;" ::: "memory");
}
__device__ __forceinline__ void cp_wait0() {
    asm volatile("cp.async.wait_group 0;" ::: "memory");
}

// ---------------- weight pack ----------------
__global__ void pack_weights(const float* __restrict__ expert_w,
                             const float* __restrict__ gate_w) {
    int idx = blockIdx.x * blockDim.x + threadIdx.x;
    if (idx >= NCOL * D_DIM) return;
    int n = idx >> 10;
    int k = idx & 1023;
    float v = 0.0f;
    if (n < 100) {
        int u = n / E_N, e = n % E_N;
        v = expert_w[(e * D_DIM + k) * U_N + u];      // expert_w[e,k,u]
    } else if (n < 120) {
        int m = n - 100;
        int t = m / E_N, e = m % E_N;
        v = gate_w[(t * D_DIM + k) * E_N + e];        // gate_w[t,k,e]
    }
    g_Wb[idx] = __float2bfloat16(v);
}

// ---------------- main fused kernel ----------------
__global__ __launch_bounds__(THREADS)
void mmoe_kernel(const float* __restrict__ x,
                 const float* __restrict__ expert_b,
                 const float* __restrict__ gate_b,
                 const float* __restrict__ ctr_w, const float* __restrict__ ctr_b,
                 const float* __restrict__ cvr_w, const float* __restrict__ cvr_b,
                 float* __restrict__ out) {
    extern __shared__ char smraw[];
    char* smem = (char*)(((uintptr_t)smraw + 1023) & ~(uintptr_t)1023);

    const int tid = threadIdx.x;
    const int wid = tid >> 5;
    const int lid = tid & 31;
    const int wm  = wid & 3;       // M block: rows wm*32 .. +31
    const int wn  = wid >> 2;      // N block: cols wn*32 .. +31
    const uint32_t SBase = smem_u32(smem);
    const uint32_t Abuf[2] = { SBase + SMEM_A0, SBase + SMEM_A1 };
    const uint32_t Bbuf[2] = { SBase + SMEM_B0, SBase + SMEM_B1 };

    const size_t tile = blockIdx.x;
    const float* xt = x + tile * (size_t)TILE_M * D_DIM;

    // ---- A staging map: row = tid>>2, colgroup = tid&3; iter i col = i*16+cg*4
    const int a_row   = tid >> 2;
    const int a_lane4 = tid & 3;
    const float* a_src = xt + (size_t)a_row * D_DIM + a_lane4 * 4;
    uint32_t a_dst[4];
    #pragma unroll
    for (int i = 0; i < 4; i++)
        a_dst[i] = sw128((uint32_t)(a_row * 128 + (i * 16 + a_lane4 * 4) * 2));

    // ---- B cp.async map: 2 x 16B per thread; q = tid*2+j -> n=q>>3, seg=q&7
    const __nv_bfloat16* b_src[2];
    uint32_t b_dst[2];
    #pragma unroll
    for (int j = 0; j < 2; j++) {
        const int q = tid * 2 + j;
        const int n = q >> 3, seg = q & 7;
        b_src[j] = g_Wb + n * D_DIM + seg * 8;
        b_dst[j] = sw128((uint32_t)(n * 128 + seg * 16));
    }

    // accumulators: 2 m-subtiles x 4 n-subtiles x 4 regs = 32
    float acc[2][4][4];
    #pragma unroll
    for (int mi = 0; mi < 2; mi++)
        #pragma unroll
        for (int ni = 0; ni < 4; ni++)
            #pragma unroll
            for (int r = 0; r < 4; r++) acc[mi][ni][r] = 0.f;

    // ldmatrix per-lane addressing within a 128B-stride tile
    const int a_lrow = lid & 15;
    const int a_lsel = (lid >> 4) * 16;
    const int b_lrow = (lid & 7) + (lid >> 4) * 8;
    const int b_lsel = ((lid >> 3) & 1) * 16;

    float4 sa[4];   // x staging regs for next chunk

    // ---- prologue: chunk 0 ----
    #pragma unroll
    for (int j = 0; j < 2; j++)
        cp_async16(Bbuf[0] + b_dst[j], b_src[j]);
    cp_commit();
    #pragma unroll
    for (int i = 0; i < 4; i++)
        sa[i] = *(const float4*)(a_src + i * 16);
    #pragma unroll
    for (int i = 0; i < 4; i++) {
        __nv_bfloat162 p0 = __floats2bfloat162_rn(sa[i].x, sa[i].y);
        __nv_bfloat162 p1 = __floats2bfloat162_rn(sa[i].z, sa[i].w);
        uint2 pk;
        pk.x = *reinterpret_cast<uint32_t*>(&p0);
        pk.y = *reinterpret_cast<uint32_t*>(&p1);
        *(uint2*)(smem + SMEM_A0 + a_dst[i]) = pk;
    }

    for (int kc = 0; kc < NCHUNK; kc++) {
        const int p = kc & 1;
        cp_wait0();          // B(kc) arrived
        __syncthreads();     // A(kc) visible; prior readers of buf p done

        if (kc + 1 < NCHUNK) {
            const int k0n = (kc + 1) * KC;
            // B(kc+1) -> other buffer (readers of it finished before the sync)
            #pragma unroll
            for (int j = 0; j < 2; j++)
                cp_async16(Bbuf[p ^ 1] + b_dst[j], b_src[j] + k0n);
            cp_commit();
            // A(kc+1) -> regs (lands under the MMA work below)
            #pragma unroll
            for (int i = 0; i < 4; i++)
                sa[i] = *(const float4*)(a_src + k0n + i * 16);
        }

        // ---- compute chunk kc from buffers p: 4 k-steps of 16 ----
        #pragma unroll
        for (int ks = 0; ks < 4; ks++) {
            const int ko = ks * 32;   // bytes
            uint32_t af[2][4];
            #pragma unroll
            for (int mi = 0; mi < 2; mi++) {
                const int m0 = wm * 32 + mi * 16;
                uint32_t addr = Abuf[p] +
                    sw128((uint32_t)((m0 + a_lrow) * 128 + ko + a_lsel));
                ldmat_x4(af[mi][0], af[mi][1], af[mi][2], af[mi][3], addr);
            }
            uint32_t bfr[4][2];
            #pragma unroll
            for (int np = 0; np < 2; np++) {
                const int n0 = wn * 32 + np * 16;
                uint32_t addr = Bbuf[p] +
                    sw128((uint32_t)((n0 + b_lrow) * 128 + ko + b_lsel));
                uint32_t r0, r1, r2, r3;
                ldmat_x4(r0, r1, r2, r3, addr);
                bfr[np * 2][0] = r0;     bfr[np * 2][1] = r1;
                bfr[np * 2 + 1][0] = r2; bfr[np * 2 + 1][1] = r3;
            }
            #pragma unroll
            for (int mi = 0; mi < 2; mi++)
                #pragma unroll
                for (int ni = 0; ni < 4; ni++)
                    mma_bf16(acc[mi][ni], af[mi], bfr[ni][0], bfr[ni][1]);
        }

        // ---- stage A(kc+1) into the other buffer (no barrier needed:
        //      buf p^1's readers all passed this iteration's sync) ----
        if (kc + 1 < NCHUNK) {
            #pragma unroll
            for (int i = 0; i < 4; i++) {
                __nv_bfloat162 p0 = __floats2bfloat162_rn(sa[i].x, sa[i].y);
                __nv_bfloat162 p1 = __floats2bfloat162_rn(sa[i].z, sa[i].w);
                uint2 pk;
                pk.x = *reinterpret_cast<uint32_t*>(&p0);
                pk.y = *reinterpret_cast<uint32_t*>(&p1);
                *(uint2*)(smem + (p ? SMEM_A0 : SMEM_A1) + a_dst[i]) = pk;
            }
        }
    }

    // ---- epilogue: accum regs -> smem D[128][129] ----
    __syncthreads();   // all compute done; D overlays the tile buffers
    float* Dsm = (float*)smem;
    {
        const int r0 = lid >> 2;
        const int c0 = (lid & 3) * 2;
        #pragma unroll
        for (int mi = 0; mi < 2; mi++) {
            #pragma unroll
            for (int ni = 0; ni < 4; ni++) {
                const int row = wm * 32 + mi * 16 + r0;
                const int col = wn * 32 + ni * 8 + c0;
                Dsm[row * D_STRIDE + col]           = acc[mi][ni][0];
                Dsm[row * D_STRIDE + col + 1]       = acc[mi][ni][1];
                Dsm[(row + 8) * D_STRIDE + col]     = acc[mi][ni][2];
                Dsm[(row + 8) * D_STRIDE + col + 1] = acc[mi][ni][3];
            }
        }
    }
    __syncthreads();

    if (tid < TILE_M) {
        const int row = tid;
        const size_t gb = tile * TILE_M + row;
        const float* Dr = Dsm + row * D_STRIDE;

        // gate softmax per task (cols 100 + t*10 + e)
        float g0[E_N], g1[E_N];
        float m0 = -1e30f, m1 = -1e30f;
        #pragma unroll
        for (int e = 0; e < E_N; e++) {
            g0[e] = Dr[100 + e] + __ldg(gate_b + e);
            g1[e] = Dr[110 + e] + __ldg(gate_b + E_N + e);
            m0 = fmaxf(m0, g0[e]);
            m1 = fmaxf(m1, g1[e]);
        }
        float s0 = 0.f, s1 = 0.f;
        #pragma unroll
        for (int e = 0; e < E_N; e++) {
            g0[e] = __expf(g0[e] - m0); s0 += g0[e];
            g1[e] = __expf(g1[e] - m1); s1 += g1[e];
        }
        const float inv0 = __frcp_rn(s0), inv1 = __frcp_rn(s1);

        // expert relu + gate-weighted mix (expert col = u*10 + e)
        float t0[U_N], t1[U_N];
        #pragma unroll
        for (int u = 0; u < U_N; u++) { t0[u] = 0.f; t1[u] = 0.f; }
        #pragma unroll
        for (int e = 0; e < E_N; e++) {
            const float w0 = g0[e] * inv0;
            const float w1 = g1[e] * inv1;
            #pragma unroll
            for (int u = 0; u < U_N; u++) {
                float h = Dr[u * E_N + e] + __ldg(expert_b + e * U_N + u);
                h = fmaxf(h, 0.f);
                t0[u] = fmaf(h, w0, t0[u]);
                t1[u] = fmaf(h, w1, t1[u]);
            }
        }
        float z0 = __ldg(ctr_b), z1 = __ldg(cvr_b);
        #pragma unroll
        for (int u = 0; u < U_N; u++) {
            z0 = fmaf(t0[u], __ldg(ctr_w + u), z0);
            z1 = fmaf(t1[u], __ldg(cvr_w + u), z1);
        }
        out[gb]          = __frcp_rn(1.f + __expf(-z0));   // ctr sigmoid
        out[B_ROWS + gb] = __frcp_rn(1.f + __expf(-z1));   // cvr sigmoid
    }
}

// ---------------- launch ----------------
extern "C" void kernel_launch(void* const* d_in, const int* in_sizes, int n_in,
                              void* d_out, int out_size) {
    const float* x        = (const float*)d_in[0];
    // d_in[1] show_index, d_in[2] st : unused by the reference
    const float* expert_w = (const float*)d_in[3];
    const float* expert_b = (const float*)d_in[4];
    const float* gate_w   = (const float*)d_in[5];
    const float* gate_b   = (const float*)d_in[6];
    const float* ctr_w    = (const float*)d_in[7];
    const float* ctr_b    = (const float*)d_in[8];
    const float* cvr_w    = (const float*)d_in[9];
    const float* cvr_b    = (const float*)d_in[10];
    float* out = (float*)d_out;

    pack_weights<<<(NCOL * D_DIM + 255) / 256, 256>>>(expert_w, gate_w);

    static bool attr_set = false;
    if (!attr_set) {
        cudaFuncSetAttribute(mmoe_kernel,
                             cudaFuncAttributeMaxDynamicSharedMemorySize, SMEM_DYN);
        attr_set = true;
    }
    mmoe_kernel<<<B_ROWS / TILE_M, THREADS, SMEM_DYN>>>(
        x, expert_b, gate_b, ctr_w, ctr_b, cvr_w, cvr_b, out);
}

// round 12
// speedup vs baseline: 1.5251x; 1.5251x over previous
#include <cuda_runtime.h>
#include <cuda_bf16.h>
#include <cstdint>

// ---------------- problem constants ----------------
#define B_ROWS   65536
#define D_DIM    1024
#define E_N      10
#define U_N      10
#define NCOL     128          // padded N (120 used: 100 expert + 20 gate)
#define TILE_M   128
#define KC       64           // K elems per chunk (64 bf16 = 128B row)
#define NCHUNK   (D_DIM / KC) // 16
#define THREADS  256          // 8 warps: 2(M) x 4(N), warp tile 64x32

// smem: single A tile (16KB) + single B tile (16KB); epilogue D[128][121] reuses
#define SMEM_A_OFF   0
#define SMEM_B_OFF   (TILE_M * 128)
#define D_STRIDE     121
#define SMEM_D_BYTES (TILE_M * D_STRIDE * 4)   // 61952 (> 32KB tiles)
#define SMEM_DYN     (SMEM_D_BYTES + 1024)

// bf16 packed weights: Wb[n][k] (B^T, K-major). n<100: expert(u=n/10,e=n%10),
// n in [100,120): gate(t,e). Rest zero padding.
__device__ __align__(16) __nv_bfloat16 g_Wb[NCOL * D_DIM];

// ---------------- helpers ----------------
__device__ __forceinline__ uint32_t smem_u32(const void* p) {
    return (uint32_t)__cvta_generic_to_shared(p);
}
__device__ __forceinline__ uint32_t sw128(uint32_t off) {
    return off ^ ((off >> 3) & 0x70);
}
__device__ __forceinline__ void ldmat_x4(uint32_t& r0, uint32_t& r1,
                                         uint32_t& r2, uint32_t& r3,
                                         uint32_t addr) {
    asm volatile("ldmatrix.sync.aligned.m8n8.x4.shared.b16 {%0,%1,%2,%3}, [%4];"
                 : "=r"(r0), "=r"(r1), "=r"(r2), "=r"(r3) : "r"(addr));
}
__device__ __forceinline__ void mma_bf16(float* c, const uint32_t* a,
                                         uint32_t b0, uint32_t b1) {
    asm volatile(
        "mma.sync.aligned.m16n8k16.row.col.f32.bf16.bf16.f32 "
        "{%0,%1,%2,%3}, {%4,%5,%6,%7}, {%8,%9}, {%0,%1,%2,%3};"
        : "+f"(c[0]), "+f"(c[1]), "+f"(c[2]), "+f"(c[3])
        : "r"(a[0]), "r"(a[1]), "r"(a[2]), "r"(a[3]), "r"(b0), "r"(b1));
}

// ---------------- weight pack ----------------
__global__ void pack_weights(const float* __restrict__ expert_w,
                             const float* __restrict__ gate_w) {
    int idx = blockIdx.x * blockDim.x + threadIdx.x;
    if (idx >= NCOL * D_DIM) return;
    int n = idx >> 10;
    int k = idx & 1023;
    float v = 0.0f;
    if (n < 100) {
        int u = n / E_N, e = n % E_N;
        v = expert_w[(e * D_DIM + k) * U_N + u];      // expert_w[e,k,u]
    } else if (n < 120) {
        int m = n - 100;
        int t = m / E_N, e = m % E_N;
        v = gate_w[(t * D_DIM + k) * E_N + e];        // gate_w[t,k,e]
    }
    g_Wb[idx] = __float2bfloat16(v);
}

// ---------------- main fused kernel ----------------
__global__ __launch_bounds__(THREADS, 2)
void mmoe_kernel(const float* __restrict__ x,
                 const float* __restrict__ expert_b,
                 const float* __restrict__ gate_b,
                 const float* __restrict__ ctr_w, const float* __restrict__ ctr_b,
                 const float* __restrict__ cvr_w, const float* __restrict__ cvr_b,
                 float* __restrict__ out) {
    extern __shared__ char smraw[];
    char* smem = (char*)(((uintptr_t)smraw + 1023) & ~(uintptr_t)1023);

    const int tid = threadIdx.x;
    const int wid = tid >> 5;
    const int lid = tid & 31;
    const int wm  = wid & 1;       // M block: rows wm*64 .. +63
    const int wn  = wid >> 1;      // N block: cols wn*32 .. +31
    const uint32_t Abase = smem_u32(smem) + SMEM_A_OFF;
    const uint32_t Bbase = smem_u32(smem) + SMEM_B_OFF;

    const size_t tile = blockIdx.x;
    const float* xt = x + tile * (size_t)TILE_M * D_DIM;

    // ---- A staging map: 8 iters; q = i*256+tid -> row=q>>4, seg=q&15 (float4)
    const int a_row0 = tid >> 4;        // +16 per iter
    const int a_seg  = tid & 15;
    const float* a_src = xt + (size_t)a_row0 * D_DIM + a_seg * 4;
    const uint32_t a_dst0 = sw128((uint32_t)(a_row0 * 128 + a_seg * 8));
    // note: sw128 only mixes bits within a 1KB block; row stride 128B means
    // +16 rows = +2048B which is swizzle-invariant, so dst(i) = a_dst0 + i*2048.

    // ---- B staging map: 4 iters; q = i*256+tid -> row=q>>3, seg=q&7 (uint4)
    const int b_row0 = tid >> 3;        // +32 per iter
    const int b_seg  = tid & 7;
    const __nv_bfloat16* b_src = g_Wb + b_row0 * D_DIM + b_seg * 8;
    const uint32_t b_dst0 = sw128((uint32_t)(b_row0 * 128 + b_seg * 16));
    // +32 rows = +4096B, swizzle-invariant: dst(i) = b_dst0 + i*4096.

    // accumulators: 4 m-subtiles x 4 n-subtiles x 4 regs = 64
    float acc[4][4][4];
    #pragma unroll
    for (int mi = 0; mi < 4; mi++)
        #pragma unroll
        for (int ni = 0; ni < 4; ni++)
            #pragma unroll
            for (int r = 0; r < 4; r++) acc[mi][ni][r] = 0.f;

    // ldmatrix per-lane addressing within a 128B-stride tile
    const int a_lrow = lid & 15;
    const int a_lsel = (lid >> 4) * 16;
    const int b_lrow = (lid & 7) + (lid >> 4) * 8;
    const int b_lsel = ((lid >> 3) & 1) * 16;

    for (int kc = 0; kc < NCHUNK; kc++) {
        const int k0 = kc * KC;

        // ---- stage A: batched LDG (MLP=8) then cvt+STS ----
        float4 fa[8];
        #pragma unroll
        for (int i = 0; i < 8; i++)
            fa[i] = *(const float4*)(a_src + (size_t)i * 16 * D_DIM + k0);
        #pragma unroll
        for (int i = 0; i < 8; i++) {
            __nv_bfloat162 p0 = __floats2bfloat162_rn(fa[i].x, fa[i].y);
            __nv_bfloat162 p1 = __floats2bfloat162_rn(fa[i].z, fa[i].w);
            uint2 pk;
            pk.x = *reinterpret_cast<uint32_t*>(&p0);
            pk.y = *reinterpret_cast<uint32_t*>(&p1);
            *(uint2*)(smem + SMEM_A_OFF + a_dst0 + i * 2048) = pk;
        }
        // ---- stage B: batched LDG (L2-resident) then STS.128 ----
        uint4 wbv[4];
        #pragma unroll
        for (int i = 0; i < 4; i++)
            wbv[i] = *(const uint4*)(b_src + i * 32 * D_DIM + k0);
        #pragma unroll
        for (int i = 0; i < 4; i++)
            *(uint4*)(smem + SMEM_B_OFF + b_dst0 + i * 4096) = wbv[i];

        __syncthreads();

        // ---- compute chunk kc: 4 k-steps of 16 ----
        #pragma unroll
        for (int ks = 0; ks < 4; ks++) {
            const int ko = ks * 32;   // bytes
            uint32_t af[4][4];
            #pragma unroll
            for (int mi = 0; mi < 4; mi++) {
                const int m0 = wm * 64 + mi * 16;
                uint32_t addr = Abase +
                    sw128((uint32_t)((m0 + a_lrow) * 128 + ko + a_lsel));
                ldmat_x4(af[mi][0], af[mi][1], af[mi][2], af[mi][3], addr);
            }
            uint32_t bfr[4][2];
            #pragma unroll
            for (int np = 0; np < 2; np++) {
                const int n0 = wn * 32 + np * 16;
                uint32_t addr = Bbase +
                    sw128((uint32_t)((n0 + b_lrow) * 128 + ko + b_lsel));
                uint32_t r0, r1, r2, r3;
                ldmat_x4(r0, r1, r2, r3, addr);
                bfr[np * 2][0] = r0;     bfr[np * 2][1] = r1;
                bfr[np * 2 + 1][0] = r2; bfr[np * 2 + 1][1] = r3;
            }
            #pragma unroll
            for (int mi = 0; mi < 4; mi++)
                #pragma unroll
                for (int ni = 0; ni < 4; ni++)
                    mma_bf16(acc[mi][ni], af[mi], bfr[ni][0], bfr[ni][1]);
        }
        __syncthreads();   // compute done before buffers are restaged
    }

    // ---- epilogue: accum regs -> smem D[128][121] ----
    float* Dsm = (float*)smem;
    {
        const int r0 = lid >> 2;
        const int c0 = (lid & 3) * 2;
        #pragma unroll
        for (int mi = 0; mi < 4; mi++) {
            #pragma unroll
            for (int ni = 0; ni < 4; ni++) {
                const int colb = wn * 32 + ni * 8;
                if (colb < 120) {     // skip padding subtile (cols 120..127)
                    const int row = wm * 64 + mi * 16 + r0;
                    const int col = colb + c0;
                    Dsm[row * D_STRIDE + col]           = acc[mi][ni][0];
                    Dsm[row * D_STRIDE + col + 1]       = acc[mi][ni][1];
                    Dsm[(row + 8) * D_STRIDE + col]     = acc[mi][ni][2];
                    Dsm[(row + 8) * D_STRIDE + col + 1] = acc[mi][ni][3];
                }
            }
        }
    }
    __syncthreads();

    if (tid < TILE_M) {
        const int row = tid;
        const size_t gb = tile * TILE_M + row;
        const float* Dr = Dsm + row * D_STRIDE;

        // gate softmax per task (cols 100 + t*10 + e)
        float g0[E_N], g1[E_N];
        float m0 = -1e30f, m1 = -1e30f;
        #pragma unroll
        for (int e = 0; e < E_N; e++) {
            g0[e] = Dr[100 + e] + __ldg(gate_b + e);
            g1[e] = Dr[110 + e] + __ldg(gate_b + E_N + e);
            m0 = fmaxf(m0, g0[e]);
            m1 = fmaxf(m1, g1[e]);
        }
        float s0 = 0.f, s1 = 0.f;
        #pragma unroll
        for (int e = 0; e < E_N; e++) {
            g0[e] = __expf(g0[e] - m0); s0 += g0[e];
            g1[e] = __expf(g1[e] - m1); s1 += g1[e];
        }
        const float inv0 = __frcp_rn(s0), inv1 = __frcp_rn(s1);

        // expert relu + gate-weighted mix (expert col = u*10 + e)
        float t0[U_N], t1[U_N];
        #pragma unroll
        for (int u = 0; u < U_N; u++) { t0[u] = 0.f; t1[u] = 0.f; }
        #pragma unroll
        for (int e = 0; e < E_N; e++) {
            const float w0 = g0[e] * inv0;
            const float w1 = g1[e] * inv1;
            #pragma unroll
            for (int u = 0; u < U_N; u++) {
                float h = Dr[u * E_N + e] + __ldg(expert_b + e * U_N + u);
                h = fmaxf(h, 0.f);
                t0[u] = fmaf(h, w0, t0[u]);
                t1[u] = fmaf(h, w1, t1[u]);
            }
        }
        float z0 = __ldg(ctr_b), z1 = __ldg(cvr_b);
        #pragma unroll
        for (int u = 0; u < U_N; u++) {
            z0 = fmaf(t0[u], __ldg(ctr_w + u), z0);
            z1 = fmaf(t1[u], __ldg(cvr_w + u), z1);
        }
        out[gb]          = __frcp_rn(1.f + __expf(-z0));   // ctr sigmoid
        out[B_ROWS + gb] = __frcp_rn(1.f + __expf(-z1));   // cvr sigmoid
    }
}

// ---------------- launch ----------------
extern "C" void kernel_launch(void* const* d_in, const int* in_sizes, int n_in,
                              void* d_out, int out_size) {
    const float* x        = (const float*)d_in[0];
    // d_in[1] show_index, d_in[2] st : unused by the reference
    const float* expert_w = (const float*)d_in[3];
    const float* expert_b = (const float*)d_in[4];
    const float* gate_w   = (const float*)d_in[5];
    const float* gate_b   = (const float*)d_in[6];
    const float* ctr_w    = (const float*)d_in[7];
    const float* ctr_b    = (const float*)d_in[8];
    const float* cvr_w    = (const float*)d_in[9];
    const float* cvr_b    = (const float*)d_in[10];
    float* out = (float*)d_out;

    pack_weights<<<(NCOL * D_DIM + 255) / 256, 256>>>(expert_w, gate_w);

    static bool attr_set = false;
    if (!attr_set) {
        cudaFuncSetAttribute(mmoe_kernel,
                             cudaFuncAttributeMaxDynamicSharedMemorySize, SMEM_DYN);
        attr_set = true;
    }
    mmoe_kernel<<<B_ROWS / TILE_M, THREADS, SMEM_DYN>>>(
        x, expert_b, gate_b, ctr_w, ctr_b, cvr_w, cvr_b, out);
}